// round 13
// baseline (speedup 1.0000x reference)
#include <cuda_runtime.h>

#define NB 4
#define NN 2048
#define FI 128
#define NH 4
#define NC 32
#define NF 128        // NH*NC
#define CAP 128       // max edges per row (mean ~21; P(>128) ~ 0)
#define NEG 0.2f

// ---- scratch (__device__ globals; no allocation allowed) ----
__device__ float g_proj[(size_t)NB * NN * NF];       // 16 MB
__device__ float g_asrc[NB * NN * NH];
__device__ float g_adst[NB * NN * NH];
__device__ float g_denom[NB * NN * NH];              // 32768 floats
__device__ float g_ew[(size_t)NB * NN * CAP * NH];   // 16 MB (sparse-used)
__device__ int   g_list[(size_t)NB * NN * CAP];      // 4 MB (sparse-used)
__device__ int   g_cnt[NB * NN];

// ---------------------------------------------------------------------------
// K1: proj = x @ W (M=8192,N=128,K=128) + fused attention dots epilogue
//     + fused g_denom zeroing.
// Same 64x128 block tile and full W+x smem staging as R4, but 512 threads
// with a 4x4 thread tile: FFMA floor unchanged, warps/SMSP 2 -> 4 for
// latency hiding, regs ~60 vs 128.
// ---------------------------------------------------------------------------
__global__ void __launch_bounds__(512, 1)
gemm_kernel(const float* __restrict__ x, const float* __restrict__ W,
            const float* __restrict__ att_src, const float* __restrict__ att_dst) {
    __shared__ float xs[64][FI];    // 32 KB
    __shared__ float ws[FI][NF];    // 64 KB

    const int tid = threadIdx.x;
    const int rowBase = blockIdx.x * 64;
    const int tx = tid & 31;        // col quad: cols tx*4 .. tx*4+3
    const int ty = tid >> 5;        // warp id 0..15: rows ty*4 .. ty*4+3

    // zero denom: 8192 float4 total / 128 blocks = 64 per block
    if (tid < 64) {
        int idx = blockIdx.x * 64 + tid;     // 0..8191
        *(float4*)&g_denom[idx * 4] = make_float4(0.f, 0.f, 0.f, 0.f);
    }

    // stage x tile: 64 rows x 32 float4 = 2048 float4, 4 per thread
#pragma unroll
    for (int it = 0; it < 4; it++) {
        int v = tid + it * 512;
        int r = v >> 5;
        int c = v & 31;
        *(float4*)&xs[r][c * 4] = *(const float4*)&x[(size_t)(rowBase + r) * FI + c * 4];
    }
    // stage full W: 128 x 32 float4 = 4096 float4, 8 per thread
#pragma unroll
    for (int it = 0; it < 8; it++) {
        int v = tid + it * 512;
        int r = v >> 5;
        int c = v & 31;
        *(float4*)&ws[r][c * 4] = *(const float4*)&W[(size_t)r * NF + c * 4];
    }
    __syncthreads();

    float acc[4][4];
#pragma unroll
    for (int r = 0; r < 4; r++)
#pragma unroll
        for (int c = 0; c < 4; c++) acc[r][c] = 0.0f;

#pragma unroll 4
    for (int kq = 0; kq < FI / 4; kq++) {
        float4 a4[4];
#pragma unroll
        for (int r = 0; r < 4; r++)
            a4[r] = *(const float4*)&xs[ty * 4 + r][kq * 4];
#pragma unroll
        for (int kk = 0; kk < 4; kk++) {
            float4 b = *(const float4*)&ws[kq * 4 + kk][tx * 4];
            float bv[4] = {b.x, b.y, b.z, b.w};
#pragma unroll
            for (int r = 0; r < 4; r++) {
                float a = (kk == 0) ? a4[r].x : (kk == 1) ? a4[r].y
                        : (kk == 2) ? a4[r].z : a4[r].w;
#pragma unroll
                for (int c = 0; c < 4; c++) acc[r][c] += a * bv[c];
            }
        }
    }

    // attention-dot weights for this thread's 4 columns (head h = tx>>3)
    float4 avs = *(const float4*)&att_src[tx * 4];
    float4 avd = *(const float4*)&att_dst[tx * 4];
    const int h = tx >> 3;

#pragma unroll
    for (int r = 0; r < 4; r++) {
        int node = rowBase + ty * 4 + r;
        *(float4*)&g_proj[(size_t)node * NF + tx * 4] =
            make_float4(acc[r][0], acc[r][1], acc[r][2], acc[r][3]);

        float s = acc[r][0] * avs.x + acc[r][1] * avs.y + acc[r][2] * avs.z + acc[r][3] * avs.w;
        float d = acc[r][0] * avd.x + acc[r][1] * avd.y + acc[r][2] * avd.z + acc[r][3] * avd.w;
        // reduce over the 8 lanes sharing this head
        s += __shfl_xor_sync(0xffffffffu, s, 1);
        d += __shfl_xor_sync(0xffffffffu, d, 1);
        s += __shfl_xor_sync(0xffffffffu, s, 2);
        d += __shfl_xor_sync(0xffffffffu, d, 2);
        s += __shfl_xor_sync(0xffffffffu, s, 4);
        d += __shfl_xor_sync(0xffffffffu, d, 4);
        if ((tx & 7) == 0) {
            g_asrc[node * NH + h] = s;
            g_adst[node * NH + h] = d;
        }
    }
}

// ---------------------------------------------------------------------------
// K2: row scan (R4-exact, fused compaction + edge processing)
// ---------------------------------------------------------------------------
__global__ void scan_kernel(const float* __restrict__ adj) {
    const int blk = blockIdx.x;            // node id = b*NN + i
    const int b = blk >> 11;
    const int i = blk & (NN - 1);
    const float4* row = (const float4*)(adj + (size_t)blk * NN);

    __shared__ int s_cnt;
    __shared__ int s_js[CAP];
    if (threadIdx.x == 0) s_cnt = 0;
    __syncthreads();

    const int tid = threadIdx.x;
    const int lane = tid & 31;

    float4 v0 = row[tid];
    float4 v1 = row[tid + 256];
    const int j0 = tid * 4;
    const int j1 = (tid + 256) * 4;

    unsigned m = 0;
    if (v0.x != 0.f || j0 + 0 == i) m |= 1u;
    if (v0.y != 0.f || j0 + 1 == i) m |= 2u;
    if (v0.z != 0.f || j0 + 2 == i) m |= 4u;
    if (v0.w != 0.f || j0 + 3 == i) m |= 8u;
    if (v1.x != 0.f || j1 + 0 == i) m |= 16u;
    if (v1.y != 0.f || j1 + 1 == i) m |= 32u;
    if (v1.z != 0.f || j1 + 2 == i) m |= 64u;
    if (v1.w != 0.f || j1 + 3 == i) m |= 128u;

    int c = __popc(m);
    int pre = c;
#pragma unroll
    for (int off = 1; off < 32; off <<= 1) {
        int n = __shfl_up_sync(0xffffffffu, pre, off);
        if (lane >= off) pre += n;
    }
    int total = __shfl_sync(0xffffffffu, pre, 31);
    int base = 0;
    if (lane == 31 && total > 0) base = atomicAdd(&s_cnt, total);
    base = __shfl_sync(0xffffffffu, base, 31);
    int pos = base + pre - c;

    while (m) {
        int k = __ffs(m) - 1;
        m &= m - 1;
        int j = (k < 4) ? (j0 + k) : (j1 + k - 4);
        if (pos < CAP) s_js[pos] = j;
        pos++;
    }
    __syncthreads();

    int cnt = s_cnt < CAP ? s_cnt : CAP;
    if (tid == 0) g_cnt[blk] = cnt;

    const float4 as = *(const float4*)&g_asrc[blk * NH];
    for (int e = tid; e < cnt; e += 256) {
        int j = s_js[e];
        int node_j = (b << 11) + j;
        float4 ad = *(const float4*)&g_adst[node_j * NH];
        float e0 = as.x + ad.x; e0 = (e0 > 0.f) ? e0 : NEG * e0; e0 = __expf(e0);
        float e1 = as.y + ad.y; e1 = (e1 > 0.f) ? e1 : NEG * e1; e1 = __expf(e1);
        float e2 = as.z + ad.z; e2 = (e2 > 0.f) ? e2 : NEG * e2; e2 = __expf(e2);
        float e3 = as.w + ad.w; e3 = (e3 > 0.f) ? e3 : NEG * e3; e3 = __expf(e3);
        g_list[(size_t)blk * CAP + e] = j;
        *(float4*)&g_ew[((size_t)blk * CAP + e) * NH] = make_float4(e0, e1, e2, e3);
        float* dn = &g_denom[node_j * NH];    // 16B aligned
        asm volatile("red.global.add.v4.f32 [%0], {%1, %2, %3, %4};"
                     :: "l"(dn), "f"(e0), "f"(e1), "f"(e2), "f"(e3) : "memory");
    }
}

// ---------------------------------------------------------------------------
// K3: aggregation — two warps per row, inner loop unrolled x4 (R12-exact).
// ---------------------------------------------------------------------------
__global__ void __launch_bounds__(256)
agg_kernel(float* __restrict__ out, const float* __restrict__ bias) {
    const int tid = threadIdx.x;
    const int wid = tid >> 5;        // 0..7
    const int lane = tid & 31;
    const int rloc = wid >> 1;       // 0..3 : local row
    const int p = wid & 1;           // half of the warp pair
    const int blk = blockIdx.x * 4 + rloc;   // row id = b*NN + i
    const int b = blk >> 11;

    __shared__ const float* ptrs[4][CAP];    // 4 KB
    __shared__ float wts[4][CAP][4];         // 8 KB
    __shared__ float pacc[4][32][4];         // 2 KB

    const int cnt = g_cnt[blk];
    const size_t bbase = (size_t)(b << 11);

    // staging: 64 threads per row
    for (int e = (tid & 63); e < cnt; e += 64) {
        int j = g_list[(size_t)blk * CAP + e];
        ptrs[rloc][e] = g_proj + (bbase + j) * NF;
        float4 ew = *(const float4*)&g_ew[((size_t)blk * CAP + e) * NH];
        float4 dn = *(const float4*)&g_denom[((b << 11) + j) * NH];
        wts[rloc][e][0] = __fdividef(ew.x, dn.x);
        wts[rloc][e][1] = __fdividef(ew.y, dn.y);
        wts[rloc][e][2] = __fdividef(ew.z, dn.z);
        wts[rloc][e][3] = __fdividef(ew.w, dn.w);
    }
    __syncthreads();

    const int h = lane >> 3;         // 4 consecutive features share one head
    const int f4 = lane * 4;
    float4 acc = make_float4(0.f, 0.f, 0.f, 0.f);

    // warp half p owns edges p, p+2, p+4, ...; process 4 per iteration
    int e = p;
    for (; e + 6 < cnt; e += 8) {
        const float* q0 = ptrs[rloc][e];
        const float* q1 = ptrs[rloc][e + 2];
        const float* q2 = ptrs[rloc][e + 4];
        const float* q3 = ptrs[rloc][e + 6];
        float w0 = wts[rloc][e][h];
        float w1 = wts[rloc][e + 2][h];
        float w2 = wts[rloc][e + 4][h];
        float w3 = wts[rloc][e + 6][h];
        float4 a0 = *(const float4*)(q0 + f4);
        float4 a1 = *(const float4*)(q1 + f4);
        float4 a2 = *(const float4*)(q2 + f4);
        float4 a3 = *(const float4*)(q3 + f4);
        acc.x += w0 * a0.x + w1 * a1.x + w2 * a2.x + w3 * a3.x;
        acc.y += w0 * a0.y + w1 * a1.y + w2 * a2.y + w3 * a3.y;
        acc.z += w0 * a0.z + w1 * a1.z + w2 * a2.z + w3 * a3.z;
        acc.w += w0 * a0.w + w1 * a1.w + w2 * a2.w + w3 * a3.w;
    }
    for (; e < cnt; e += 2) {
        const float* q0 = ptrs[rloc][e];
        float w0 = wts[rloc][e][h];
        float4 a0 = *(const float4*)(q0 + f4);
        acc.x += w0 * a0.x;
        acc.y += w0 * a0.y;
        acc.z += w0 * a0.z;
        acc.w += w0 * a0.w;
    }

    // combine the two halves
    if (p == 1) *(float4*)&pacc[rloc][lane][0] = acc;
    __syncthreads();
    if (p == 0) {
        float4 o = *(const float4*)&pacc[rloc][lane][0];
        float4 bv = *(const float4*)&bias[f4];
        acc.x += o.x + bv.x;
        acc.y += o.y + bv.y;
        acc.z += o.z + bv.z;
        acc.w += o.w + bv.w;
        *(float4*)&out[(size_t)blk * NF + f4] = acc;
    }
}

// ---------------------------------------------------------------------------
extern "C" void kernel_launch(void* const* d_in, const int* in_sizes, int n_in,
                              void* d_out, int out_size) {
    const float* x       = (const float*)d_in[0];  // [B,N,F_IN]
    const float* adj     = (const float*)d_in[1];  // [B,N,N]
    const float* W       = (const float*)d_in[2];  // [F_IN, H*C]
    const float* att_src = (const float*)d_in[3];  // [H,C]
    const float* att_dst = (const float*)d_in[4];  // [H,C]
    const float* bias    = (const float*)d_in[5];  // [H*C]
    float* out = (float*)d_out;

    gemm_kernel<<<(NB * NN) / 64, 512>>>(x, W, att_src, att_dst);
    scan_kernel<<<NB * NN, 256>>>(adj);
    agg_kernel<<<(NB * NN) / 4, 256>>>(out, bias);
}

// round 14
// speedup vs baseline: 1.0558x; 1.0558x over previous
#include <cuda_runtime.h>

#define NB 4
#define NN 2048
#define FI 128
#define NH 4
#define NC 32
#define NF 128        // NH*NC
#define CAP 128       // max edges per row (mean ~21; P(>128) ~ 0)
#define NEG 0.2f

// ---- scratch (__device__ globals; no allocation allowed) ----
__device__ float g_proj[(size_t)NB * NN * NF];       // 16 MB
__device__ float g_asrc[NB * NN * NH];
__device__ float g_adst[NB * NN * NH];
__device__ float g_denom[NB * NN * NH];              // 32768 floats
__device__ float g_ew[(size_t)NB * NN * CAP * NH];   // 16 MB (sparse-used)
__device__ int   g_list[(size_t)NB * NN * CAP];      // 4 MB (sparse-used)
__device__ int   g_cnt[NB * NN];

// ---------------------------------------------------------------------------
// K1: proj = x @ W (M=8192,N=128,K=128) + fused attention dots epilogue
//     + fused g_denom zeroing.  (R12-exact math; + PDL trigger)
// ---------------------------------------------------------------------------
__global__ void __launch_bounds__(256, 1)
gemm_kernel(const float* __restrict__ x, const float* __restrict__ W,
            const float* __restrict__ att_src, const float* __restrict__ att_dst) {
    __shared__ float xs[64][FI];    // 32 KB
    __shared__ float ws[FI][NF];    // 64 KB

    const int tid = threadIdx.x;
    const int rowBase = blockIdx.x * 64;
    const int tx = tid & 31;        // col quad: cols tx*4 .. tx*4+3
    const int ty = tid >> 5;        // row group: rows ty*8 .. ty*8+7

    // zero denom: 8192 float4 total / 128 blocks = 64 per block
    if (tid < 64) {
        int idx = blockIdx.x * 64 + tid;     // 0..8191
        *(float4*)&g_denom[idx * 4] = make_float4(0.f, 0.f, 0.f, 0.f);
    }

    // PDL: allow the dependent (scan) grid to launch now — its compaction
    // phase touches only adj and overlaps with this kernel's FFMA work.
    asm volatile("griddepcontrol.launch_dependents;");

    // stage x tile: 64 rows x 32 float4 = 2048 float4, 8 per thread
#pragma unroll
    for (int it = 0; it < 8; it++) {
        int v = tid + it * 256;
        int r = v >> 5;
        int c = v & 31;
        *(float4*)&xs[r][c * 4] = *(const float4*)&x[(size_t)(rowBase + r) * FI + c * 4];
    }
    // stage full W: 128 x 32 float4 = 4096 float4, 16 per thread
#pragma unroll
    for (int it = 0; it < 16; it++) {
        int v = tid + it * 256;
        int r = v >> 5;
        int c = v & 31;
        *(float4*)&ws[r][c * 4] = *(const float4*)&W[(size_t)r * NF + c * 4];
    }
    __syncthreads();

    float acc[8][4];
#pragma unroll
    for (int r = 0; r < 8; r++)
#pragma unroll
        for (int c = 0; c < 4; c++) acc[r][c] = 0.0f;

#pragma unroll 4
    for (int kq = 0; kq < FI / 4; kq++) {
        float4 a4[8];
#pragma unroll
        for (int r = 0; r < 8; r++)
            a4[r] = *(const float4*)&xs[ty * 8 + r][kq * 4];
#pragma unroll
        for (int kk = 0; kk < 4; kk++) {
            float4 b = *(const float4*)&ws[kq * 4 + kk][tx * 4];
            float bv[4] = {b.x, b.y, b.z, b.w};
#pragma unroll
            for (int r = 0; r < 8; r++) {
                float a = (kk == 0) ? a4[r].x : (kk == 1) ? a4[r].y
                        : (kk == 2) ? a4[r].z : a4[r].w;
#pragma unroll
                for (int c = 0; c < 4; c++) acc[r][c] += a * bv[c];
            }
        }
    }

    float4 avs = *(const float4*)&att_src[tx * 4];
    float4 avd = *(const float4*)&att_dst[tx * 4];
    const int h = tx >> 3;

#pragma unroll
    for (int r = 0; r < 8; r++) {
        int node = rowBase + ty * 8 + r;
        *(float4*)&g_proj[(size_t)node * NF + tx * 4] =
            make_float4(acc[r][0], acc[r][1], acc[r][2], acc[r][3]);

        float s = acc[r][0] * avs.x + acc[r][1] * avs.y + acc[r][2] * avs.z + acc[r][3] * avs.w;
        float d = acc[r][0] * avd.x + acc[r][1] * avd.y + acc[r][2] * avd.z + acc[r][3] * avd.w;
        s += __shfl_xor_sync(0xffffffffu, s, 1);
        d += __shfl_xor_sync(0xffffffffu, d, 1);
        s += __shfl_xor_sync(0xffffffffu, s, 2);
        d += __shfl_xor_sync(0xffffffffu, d, 2);
        s += __shfl_xor_sync(0xffffffffu, s, 4);
        d += __shfl_xor_sync(0xffffffffu, d, 4);
        if ((tx & 7) == 0) {
            g_asrc[node * NH + h] = s;
            g_adst[node * NH + h] = d;
        }
    }
}

// ---------------------------------------------------------------------------
// K2: row scan — PDL dependent.  Phase 1 (compaction, adj-only) runs
// CONCURRENTLY with gemm; griddepcontrol.wait then guarantees gemm's
// asrc/adst writes are visible before the exp/denom phase.
// ---------------------------------------------------------------------------
__global__ void scan_kernel(const float* __restrict__ adj) {
    const int blk = blockIdx.x;            // node id = b*NN + i
    const int b = blk >> 11;
    const int i = blk & (NN - 1);
    const float4* row = (const float4*)(adj + (size_t)blk * NN);

    __shared__ int s_cnt;
    __shared__ int s_js[CAP];
    if (threadIdx.x == 0) s_cnt = 0;
    __syncthreads();

    const int tid = threadIdx.x;
    const int lane = tid & 31;

    float4 v0 = row[tid];
    float4 v1 = row[tid + 256];
    const int j0 = tid * 4;
    const int j1 = (tid + 256) * 4;

    unsigned m = 0;
    if (v0.x != 0.f || j0 + 0 == i) m |= 1u;
    if (v0.y != 0.f || j0 + 1 == i) m |= 2u;
    if (v0.z != 0.f || j0 + 2 == i) m |= 4u;
    if (v0.w != 0.f || j0 + 3 == i) m |= 8u;
    if (v1.x != 0.f || j1 + 0 == i) m |= 16u;
    if (v1.y != 0.f || j1 + 1 == i) m |= 32u;
    if (v1.z != 0.f || j1 + 2 == i) m |= 64u;
    if (v1.w != 0.f || j1 + 3 == i) m |= 128u;

    int c = __popc(m);
    int pre = c;
#pragma unroll
    for (int off = 1; off < 32; off <<= 1) {
        int n = __shfl_up_sync(0xffffffffu, pre, off);
        if (lane >= off) pre += n;
    }
    int total = __shfl_sync(0xffffffffu, pre, 31);
    int base = 0;
    if (lane == 31 && total > 0) base = atomicAdd(&s_cnt, total);
    base = __shfl_sync(0xffffffffu, base, 31);
    int pos = base + pre - c;

    while (m) {
        int k = __ffs(m) - 1;
        m &= m - 1;
        int j = (k < 4) ? (j0 + k) : (j1 + k - 4);
        if (pos < CAP) s_js[pos] = j;
        pos++;
    }
    __syncthreads();

    int cnt = s_cnt < CAP ? s_cnt : CAP;
    if (tid == 0) g_cnt[blk] = cnt;

    // ---- wait for gemm completion (asrc/adst/denom-zero visible) ----
    asm volatile("griddepcontrol.wait;" ::: "memory");

    const float4 as = *(const float4*)&g_asrc[blk * NH];
    for (int e = tid; e < cnt; e += 256) {
        int j = s_js[e];
        int node_j = (b << 11) + j;
        float4 ad = *(const float4*)&g_adst[node_j * NH];
        float e0 = as.x + ad.x; e0 = (e0 > 0.f) ? e0 : NEG * e0; e0 = __expf(e0);
        float e1 = as.y + ad.y; e1 = (e1 > 0.f) ? e1 : NEG * e1; e1 = __expf(e1);
        float e2 = as.z + ad.z; e2 = (e2 > 0.f) ? e2 : NEG * e2; e2 = __expf(e2);
        float e3 = as.w + ad.w; e3 = (e3 > 0.f) ? e3 : NEG * e3; e3 = __expf(e3);
        g_list[(size_t)blk * CAP + e] = j;
        *(float4*)&g_ew[((size_t)blk * CAP + e) * NH] = make_float4(e0, e1, e2, e3);
        float* dn = &g_denom[node_j * NH];    // 16B aligned
        asm volatile("red.global.add.v4.f32 [%0], {%1, %2, %3, %4};"
                     :: "l"(dn), "f"(e0), "f"(e1), "f"(e2), "f"(e3) : "memory");
    }
}

// ---------------------------------------------------------------------------
// K3: aggregation — two warps per row, inner loop unrolled x4 (R12-exact).
// ---------------------------------------------------------------------------
__global__ void __launch_bounds__(256)
agg_kernel(float* __restrict__ out, const float* __restrict__ bias) {
    const int tid = threadIdx.x;
    const int wid = tid >> 5;        // 0..7
    const int lane = tid & 31;
    const int rloc = wid >> 1;       // 0..3 : local row
    const int p = wid & 1;           // half of the warp pair
    const int blk = blockIdx.x * 4 + rloc;   // row id = b*NN + i
    const int b = blk >> 11;

    __shared__ const float* ptrs[4][CAP];    // 4 KB
    __shared__ float wts[4][CAP][4];         // 8 KB
    __shared__ float pacc[4][32][4];         // 2 KB

    const int cnt = g_cnt[blk];
    const size_t bbase = (size_t)(b << 11);

    for (int e = (tid & 63); e < cnt; e += 64) {
        int j = g_list[(size_t)blk * CAP + e];
        ptrs[rloc][e] = g_proj + (bbase + j) * NF;
        float4 ew = *(const float4*)&g_ew[((size_t)blk * CAP + e) * NH];
        float4 dn = *(const float4*)&g_denom[((b << 11) + j) * NH];
        wts[rloc][e][0] = __fdividef(ew.x, dn.x);
        wts[rloc][e][1] = __fdividef(ew.y, dn.y);
        wts[rloc][e][2] = __fdividef(ew.z, dn.z);
        wts[rloc][e][3] = __fdividef(ew.w, dn.w);
    }
    __syncthreads();

    const int h = lane >> 3;
    const int f4 = lane * 4;
    float4 acc = make_float4(0.f, 0.f, 0.f, 0.f);

    int e = p;
    for (; e + 6 < cnt; e += 8) {
        const float* q0 = ptrs[rloc][e];
        const float* q1 = ptrs[rloc][e + 2];
        const float* q2 = ptrs[rloc][e + 4];
        const float* q3 = ptrs[rloc][e + 6];
        float w0 = wts[rloc][e][h];
        float w1 = wts[rloc][e + 2][h];
        float w2 = wts[rloc][e + 4][h];
        float w3 = wts[rloc][e + 6][h];
        float4 a0 = *(const float4*)(q0 + f4);
        float4 a1 = *(const float4*)(q1 + f4);
        float4 a2 = *(const float4*)(q2 + f4);
        float4 a3 = *(const float4*)(q3 + f4);
        acc.x += w0 * a0.x + w1 * a1.x + w2 * a2.x + w3 * a3.x;
        acc.y += w0 * a0.y + w1 * a1.y + w2 * a2.y + w3 * a3.y;
        acc.z += w0 * a0.z + w1 * a1.z + w2 * a2.z + w3 * a3.z;
        acc.w += w0 * a0.w + w1 * a1.w + w2 * a2.w + w3 * a3.w;
    }
    for (; e < cnt; e += 2) {
        const float* q0 = ptrs[rloc][e];
        float w0 = wts[rloc][e][h];
        float4 a0 = *(const float4*)(q0 + f4);
        acc.x += w0 * a0.x;
        acc.y += w0 * a0.y;
        acc.z += w0 * a0.z;
        acc.w += w0 * a0.w;
    }

    if (p == 1) *(float4*)&pacc[rloc][lane][0] = acc;
    __syncthreads();
    if (p == 0) {
        float4 o = *(const float4*)&pacc[rloc][lane][0];
        float4 bv = *(const float4*)&bias[f4];
        acc.x += o.x + bv.x;
        acc.y += o.y + bv.y;
        acc.z += o.z + bv.z;
        acc.w += o.w + bv.w;
        *(float4*)&out[(size_t)blk * NF + f4] = acc;
    }
}

// ---------------------------------------------------------------------------
extern "C" void kernel_launch(void* const* d_in, const int* in_sizes, int n_in,
                              void* d_out, int out_size) {
    const float* x       = (const float*)d_in[0];  // [B,N,F_IN]
    const float* adj     = (const float*)d_in[1];  // [B,N,N]
    const float* W       = (const float*)d_in[2];  // [F_IN, H*C]
    const float* att_src = (const float*)d_in[3];  // [H,C]
    const float* att_dst = (const float*)d_in[4];  // [H,C]
    const float* bias    = (const float*)d_in[5];  // [H*C]
    float* out = (float*)d_out;

    gemm_kernel<<<(NB * NN) / 64, 256>>>(x, W, att_src, att_dst);

    // scan with Programmatic Dependent Launch: may start during gemm;
    // its griddepcontrol.wait gates the phase that consumes gemm output.
    {
        cudaLaunchConfig_t cfg = {};
        cfg.gridDim = dim3(NB * NN);
        cfg.blockDim = dim3(256);
        cfg.dynamicSmemBytes = 0;
        cfg.stream = 0;
        cudaLaunchAttribute attrs[1];
        attrs[0].id = cudaLaunchAttributeProgrammaticStreamSerialization;
        attrs[0].val.programmaticStreamSerializationAllowed = 1;
        cfg.attrs = attrs;
        cfg.numAttrs = 1;
        cudaLaunchKernelEx(&cfg, scan_kernel, adj);
    }

    agg_kernel<<<(NB * NN) / 4, 256>>>(out, bias);
}

// round 15
// speedup vs baseline: 1.0634x; 1.0072x over previous
#include <cuda_runtime.h>

#define NB 4
#define NN 2048
#define FI 128
#define NH 4
#define NC 32
#define NF 128        // NH*NC
#define CAP 128       // max edges per row (mean ~21; P(>128) ~ 0)
#define NEG 0.2f

// ---- scratch (__device__ globals; no allocation allowed) ----
__device__ float g_proj[(size_t)NB * NN * NF];       // 16 MB
__device__ float g_asrc[NB * NN * NH];
__device__ float g_adst[NB * NN * NH];
__device__ float g_denom[NB * NN * NH];              // 32768 floats
__device__ float g_ew[(size_t)NB * NN * CAP * NH];   // 16 MB (sparse-used)
__device__ int   g_list[(size_t)NB * NN * CAP];      // 4 MB (sparse-used)
__device__ int   g_cnt[NB * NN];

// ---------------------------------------------------------------------------
// K1: proj = x @ W (M=8192,N=128,K=128) + fused attention dots epilogue
//     + fused g_denom zeroing.  (R12-exact math; PDL trigger)
// ---------------------------------------------------------------------------
__global__ void __launch_bounds__(256, 1)
gemm_kernel(const float* __restrict__ x, const float* __restrict__ W,
            const float* __restrict__ att_src, const float* __restrict__ att_dst) {
    __shared__ float xs[64][FI];    // 32 KB
    __shared__ float ws[FI][NF];    // 64 KB

    const int tid = threadIdx.x;
    const int rowBase = blockIdx.x * 64;
    const int tx = tid & 31;        // col quad: cols tx*4 .. tx*4+3
    const int ty = tid >> 5;        // row group: rows ty*8 .. ty*8+7

    // zero denom: 8192 float4 total / 128 blocks = 64 per block
    if (tid < 64) {
        int idx = blockIdx.x * 64 + tid;     // 0..8191
        *(float4*)&g_denom[idx * 4] = make_float4(0.f, 0.f, 0.f, 0.f);
    }

    // PDL: let the compaction grid start now — it reads only adj and has
    // NO dependence on this kernel (it never calls griddepcontrol.wait).
    asm volatile("griddepcontrol.launch_dependents;");

    // stage x tile: 64 rows x 32 float4 = 2048 float4, 8 per thread
#pragma unroll
    for (int it = 0; it < 8; it++) {
        int v = tid + it * 256;
        int r = v >> 5;
        int c = v & 31;
        *(float4*)&xs[r][c * 4] = *(const float4*)&x[(size_t)(rowBase + r) * FI + c * 4];
    }
    // stage full W: 128 x 32 float4 = 4096 float4, 16 per thread
#pragma unroll
    for (int it = 0; it < 16; it++) {
        int v = tid + it * 256;
        int r = v >> 5;
        int c = v & 31;
        *(float4*)&ws[r][c * 4] = *(const float4*)&W[(size_t)r * NF + c * 4];
    }
    __syncthreads();

    float acc[8][4];
#pragma unroll
    for (int r = 0; r < 8; r++)
#pragma unroll
        for (int c = 0; c < 4; c++) acc[r][c] = 0.0f;

#pragma unroll 4
    for (int kq = 0; kq < FI / 4; kq++) {
        float4 a4[8];
#pragma unroll
        for (int r = 0; r < 8; r++)
            a4[r] = *(const float4*)&xs[ty * 8 + r][kq * 4];
#pragma unroll
        for (int kk = 0; kk < 4; kk++) {
            float4 b = *(const float4*)&ws[kq * 4 + kk][tx * 4];
            float bv[4] = {b.x, b.y, b.z, b.w};
#pragma unroll
            for (int r = 0; r < 8; r++) {
                float a = (kk == 0) ? a4[r].x : (kk == 1) ? a4[r].y
                        : (kk == 2) ? a4[r].z : a4[r].w;
#pragma unroll
                for (int c = 0; c < 4; c++) acc[r][c] += a * bv[c];
            }
        }
    }

    float4 avs = *(const float4*)&att_src[tx * 4];
    float4 avd = *(const float4*)&att_dst[tx * 4];
    const int h = tx >> 3;

#pragma unroll
    for (int r = 0; r < 8; r++) {
        int node = rowBase + ty * 8 + r;
        *(float4*)&g_proj[(size_t)node * NF + tx * 4] =
            make_float4(acc[r][0], acc[r][1], acc[r][2], acc[r][3]);

        float s = acc[r][0] * avs.x + acc[r][1] * avs.y + acc[r][2] * avs.z + acc[r][3] * avs.w;
        float d = acc[r][0] * avd.x + acc[r][1] * avd.y + acc[r][2] * avd.z + acc[r][3] * avd.w;
        s += __shfl_xor_sync(0xffffffffu, s, 1);
        d += __shfl_xor_sync(0xffffffffu, d, 1);
        s += __shfl_xor_sync(0xffffffffu, s, 2);
        d += __shfl_xor_sync(0xffffffffu, d, 2);
        s += __shfl_xor_sync(0xffffffffu, s, 4);
        d += __shfl_xor_sync(0xffffffffu, d, 4);
        if ((tx & 7) == 0) {
            g_asrc[node * NH + h] = s;
            g_adst[node * NH + h] = d;
        }
    }
}

// ---------------------------------------------------------------------------
// K2: adj compaction (PDL dependent, NO griddepcontrol.wait — zero
// dependence on gemm; CTAs retire immediately so the stream keeps flowing
// and the 67MB adj read overlaps gemm's FFMA window).
// ---------------------------------------------------------------------------
__global__ void compact_kernel(const float* __restrict__ adj) {
    const int blk = blockIdx.x;            // node id = b*NN + i
    const int i = blk & (NN - 1);
    const float4* row = (const float4*)(adj + (size_t)blk * NN);

    __shared__ int s_cnt;
    if (threadIdx.x == 0) s_cnt = 0;
    __syncthreads();

    const int tid = threadIdx.x;
    const int lane = tid & 31;

    float4 v0 = row[tid];
    float4 v1 = row[tid + 256];
    const int j0 = tid * 4;
    const int j1 = (tid + 256) * 4;

    unsigned m = 0;
    if (v0.x != 0.f || j0 + 0 == i) m |= 1u;
    if (v0.y != 0.f || j0 + 1 == i) m |= 2u;
    if (v0.z != 0.f || j0 + 2 == i) m |= 4u;
    if (v0.w != 0.f || j0 + 3 == i) m |= 8u;
    if (v1.x != 0.f || j1 + 0 == i) m |= 16u;
    if (v1.y != 0.f || j1 + 1 == i) m |= 32u;
    if (v1.z != 0.f || j1 + 2 == i) m |= 64u;
    if (v1.w != 0.f || j1 + 3 == i) m |= 128u;

    int c = __popc(m);
    int pre = c;
#pragma unroll
    for (int off = 1; off < 32; off <<= 1) {
        int n = __shfl_up_sync(0xffffffffu, pre, off);
        if (lane >= off) pre += n;
    }
    int total = __shfl_sync(0xffffffffu, pre, 31);
    int base = 0;
    if (lane == 31 && total > 0) base = atomicAdd(&s_cnt, total);
    base = __shfl_sync(0xffffffffu, base, 31);
    int pos = base + pre - c;

    while (m) {
        int k = __ffs(m) - 1;
        m &= m - 1;
        int j = (k < 4) ? (j0 + k) : (j1 + k - 4);
        if (pos < CAP) g_list[(size_t)blk * CAP + pos] = j;
        pos++;
    }
    __syncthreads();
    if (tid == 0) g_cnt[blk] = (s_cnt < CAP) ? s_cnt : CAP;
}

// ---------------------------------------------------------------------------
// K3: per-edge kernel, one warp per row (runs after gemm+compact by
// stream order).  ew + denom RED.
// ---------------------------------------------------------------------------
__global__ void edge_kernel() {
    const int warp = (blockIdx.x * blockDim.x + threadIdx.x) >> 5;  // row id
    const int lane = threadIdx.x & 31;
    const int blk = warp;
    const int b = blk >> 11;

    const int cnt = g_cnt[blk];
    const float4 as = *(const float4*)&g_asrc[blk * NH];

    for (int e = lane; e < cnt; e += 32) {
        int j = g_list[(size_t)blk * CAP + e];
        int node_j = (b << 11) + j;
        float4 ad = *(const float4*)&g_adst[node_j * NH];
        float e0 = as.x + ad.x; e0 = (e0 > 0.f) ? e0 : NEG * e0; e0 = __expf(e0);
        float e1 = as.y + ad.y; e1 = (e1 > 0.f) ? e1 : NEG * e1; e1 = __expf(e1);
        float e2 = as.z + ad.z; e2 = (e2 > 0.f) ? e2 : NEG * e2; e2 = __expf(e2);
        float e3 = as.w + ad.w; e3 = (e3 > 0.f) ? e3 : NEG * e3; e3 = __expf(e3);
        *(float4*)&g_ew[((size_t)blk * CAP + e) * NH] = make_float4(e0, e1, e2, e3);
        float* dn = &g_denom[node_j * NH];    // 16B aligned
        asm volatile("red.global.add.v4.f32 [%0], {%1, %2, %3, %4};"
                     :: "l"(dn), "f"(e0), "f"(e1), "f"(e2), "f"(e3) : "memory");
    }
}

// ---------------------------------------------------------------------------
// K4: aggregation — two warps per row, inner loop unrolled x4 (R12-exact).
// ---------------------------------------------------------------------------
__global__ void __launch_bounds__(256)
agg_kernel(float* __restrict__ out, const float* __restrict__ bias) {
    const int tid = threadIdx.x;
    const int wid = tid >> 5;        // 0..7
    const int lane = tid & 31;
    const int rloc = wid >> 1;       // 0..3 : local row
    const int p = wid & 1;           // half of the warp pair
    const int blk = blockIdx.x * 4 + rloc;   // row id = b*NN + i
    const int b = blk >> 11;

    __shared__ const float* ptrs[4][CAP];    // 4 KB
    __shared__ float wts[4][CAP][4];         // 8 KB
    __shared__ float pacc[4][32][4];         // 2 KB

    const int cnt = g_cnt[blk];
    const size_t bbase = (size_t)(b << 11);

    for (int e = (tid & 63); e < cnt; e += 64) {
        int j = g_list[(size_t)blk * CAP + e];
        ptrs[rloc][e] = g_proj + (bbase + j) * NF;
        float4 ew = *(const float4*)&g_ew[((size_t)blk * CAP + e) * NH];
        float4 dn = *(const float4*)&g_denom[((b << 11) + j) * NH];
        wts[rloc][e][0] = __fdividef(ew.x, dn.x);
        wts[rloc][e][1] = __fdividef(ew.y, dn.y);
        wts[rloc][e][2] = __fdividef(ew.z, dn.z);
        wts[rloc][e][3] = __fdividef(ew.w, dn.w);
    }
    __syncthreads();

    const int h = lane >> 3;
    const int f4 = lane * 4;
    float4 acc = make_float4(0.f, 0.f, 0.f, 0.f);

    int e = p;
    for (; e + 6 < cnt; e += 8) {
        const float* q0 = ptrs[rloc][e];
        const float* q1 = ptrs[rloc][e + 2];
        const float* q2 = ptrs[rloc][e + 4];
        const float* q3 = ptrs[rloc][e + 6];
        float w0 = wts[rloc][e][h];
        float w1 = wts[rloc][e + 2][h];
        float w2 = wts[rloc][e + 4][h];
        float w3 = wts[rloc][e + 6][h];
        float4 a0 = *(const float4*)(q0 + f4);
        float4 a1 = *(const float4*)(q1 + f4);
        float4 a2 = *(const float4*)(q2 + f4);
        float4 a3 = *(const float4*)(q3 + f4);
        acc.x += w0 * a0.x + w1 * a1.x + w2 * a2.x + w3 * a3.x;
        acc.y += w0 * a0.y + w1 * a1.y + w2 * a2.y + w3 * a3.y;
        acc.z += w0 * a0.z + w1 * a1.z + w2 * a2.z + w3 * a3.z;
        acc.w += w0 * a0.w + w1 * a1.w + w2 * a2.w + w3 * a3.w;
    }
    for (; e < cnt; e += 2) {
        const float* q0 = ptrs[rloc][e];
        float w0 = wts[rloc][e][h];
        float4 a0 = *(const float4*)(q0 + f4);
        acc.x += w0 * a0.x;
        acc.y += w0 * a0.y;
        acc.z += w0 * a0.z;
        acc.w += w0 * a0.w;
    }

    if (p == 1) *(float4*)&pacc[rloc][lane][0] = acc;
    __syncthreads();
    if (p == 0) {
        float4 o = *(const float4*)&pacc[rloc][lane][0];
        float4 bv = *(const float4*)&bias[f4];
        acc.x += o.x + bv.x;
        acc.y += o.y + bv.y;
        acc.z += o.z + bv.z;
        acc.w += o.w + bv.w;
        *(float4*)&out[(size_t)blk * NF + f4] = acc;
    }
}

// ---------------------------------------------------------------------------
extern "C" void kernel_launch(void* const* d_in, const int* in_sizes, int n_in,
                              void* d_out, int out_size) {
    const float* x       = (const float*)d_in[0];  // [B,N,F_IN]
    const float* adj     = (const float*)d_in[1];  // [B,N,N]
    const float* W       = (const float*)d_in[2];  // [F_IN, H*C]
    const float* att_src = (const float*)d_in[3];  // [H,C]
    const float* att_dst = (const float*)d_in[4];  // [H,C]
    const float* bias    = (const float*)d_in[5];  // [H*C]
    float* out = (float*)d_out;

    gemm_kernel<<<(NB * NN) / 64, 256>>>(x, W, att_src, att_dst);

    // compaction with PDL: starts during gemm, never waits on it.
    {
        cudaLaunchConfig_t cfg = {};
        cfg.gridDim = dim3(NB * NN);
        cfg.blockDim = dim3(256);
        cfg.dynamicSmemBytes = 0;
        cfg.stream = 0;
        cudaLaunchAttribute attrs[1];
        attrs[0].id = cudaLaunchAttributeProgrammaticStreamSerialization;
        attrs[0].val.programmaticStreamSerializationAllowed = 1;
        cfg.attrs = attrs;
        cfg.numAttrs = 1;
        cudaLaunchKernelEx(&cfg, compact_kernel, adj);
    }

    edge_kernel<<<(NB * NN) / 8, 256>>>();
    agg_kernel<<<(NB * NN) / 4, 256>>>(out, bias);
}